// round 13
// baseline (speedup 1.0000x reference)
#include <cuda_runtime.h>
#include <cuda_fp16.h>
#include <cstdint>

// Grouped conv2d via implicit GEMM on mma.sync (HMMA), single-pass fp16.
// x[16,256,128,128] * W[512,16,3,3] (groups=16) + b -> out[16,512,128,128]
// R13: row-paired warp tiles (2 rows x 32 px per warp, two 16-px halves) with
//      a 2-slot rolling B cache: each x fragment load feeds BOTH output rows.
//      W = A operand (m16k16), x = B operand (n8k16). 512 thr, 2 CTA/SM.

#define THREADS 512
#define ROWS 8

// ---- smem layout (bytes) ----
#define SWF_OFF   0
#define SWF_BYTES (9 * 1024)                // W frags: 9 taps x 32 lanes x 32B
#define XCOL_STRIDE 32
#define XROW_STRIDE (130 * XCOL_STRIDE)     // 4160
#define SX_OFF    SWF_BYTES                 // 9216
#define SX_BYTES  (10 * XROW_STRIDE)        // 41600 (ROWS+2 halo rows)
#define SBIAS_OFF (SX_OFF + SX_BYTES)       // 50816
#define SMEM_TOTAL (SBIAS_OFF + 128)        // 50944  (x2 CTA = 102KB <= 228KB)

__device__ __forceinline__ void mma16816(float& c0, float& c1, float& c2, float& c3,
                                         uint32_t a0, uint32_t a1, uint32_t a2, uint32_t a3,
                                         uint32_t b0, uint32_t b1) {
    asm volatile("mma.sync.aligned.m16n8k16.row.col.f32.f16.f16.f32 "
                 "{%0,%1,%2,%3}, {%4,%5,%6,%7}, {%8,%9}, {%0,%1,%2,%3};"
                 : "+f"(c0), "+f"(c1), "+f"(c2), "+f"(c3)
                 : "r"(a0), "r"(a1), "r"(a2), "r"(a3), "r"(b0), "r"(b1));
}

__device__ __forceinline__ uint32_t h2pack(float v0, float v1) {
    __half2 h = __floats2half2_rn(v0, v1);
    return *(uint32_t*)&h;
}

// fold addr bit7 into bit4 (16B-block xor; preserves 16B alignment)
__device__ __forceinline__ uint32_t xswz(uint32_t a) {
    return a ^ (((a >> 7) & 1u) << 4);
}

__global__ __launch_bounds__(THREADS, 2)
void grouped_conv_hmma(const float* __restrict__ x,
                       const float* __restrict__ w,
                       const float* __restrict__ bias,
                       float* __restrict__ out)
{
    extern __shared__ char smem[];
    char* swf = smem + SWF_OFF;
    char* sx  = smem + SX_OFF;
    float* sbias = (float*)(smem + SBIAS_OFF);

    const int tid = threadIdx.x;
    const int wid = tid >> 5;
    const int lane = tid & 31;

    const int hb = blockIdx.x;          // 0..15  (8-row blocks)
    const int ng = blockIdx.y;          // 0..255
    const int n  = ng >> 4;
    const int g  = ng & 15;
    const int h0 = hb * ROWS;

    // ---- stage x: rows h0-1..h0+8 (sr 0..9), cols c 0..129 (gw = c-1) ----
    const float* xg = x + (size_t)(n * 256 + g * 16) * 16384;
    for (int idx = tid; idx < 10 * 2 * 130; idx += THREADS) {
        int c  = idx % 130;
        int t  = idx / 130;
        int hf = t & 1;                 // ci half: pairs 4hf..4hf+3
        int r  = t >> 1;                // 0..9
        int gh = h0 - 1 + r;
        int gw = c - 1;
        uint4 u = make_uint4(0u, 0u, 0u, 0u);
        if ((unsigned)gh < 128u && (unsigned)gw < 128u) {
            const float* p = xg + (size_t)(hf * 8) * 16384 + gh * 128 + gw;
            float v0 = p[0];
            float v1 = p[16384];
            float v2 = p[2 * 16384];
            float v3 = p[3 * 16384];
            float v4 = p[4 * 16384];
            float v5 = p[5 * 16384];
            float v6 = p[6 * 16384];
            float v7 = p[7 * 16384];
            u.x = h2pack(v0, v1);
            u.y = h2pack(v2, v3);
            u.z = h2pack(v4, v5);
            u.w = h2pack(v6, v7);
        }
        uint32_t lg = (uint32_t)(r * XROW_STRIDE + c * XCOL_STRIDE + hf * 16);
        *(uint4*)(sx + xswz(lg)) = u;
    }

    // ---- stage W as A fragments (m16k16) ----
    const float* wgp = w + (size_t)(g * 32) * 144;
    for (int idx = tid; idx < 9 * 32 * 8; idx += THREADS) {
        int slot  = idx & 7;
        int lane2 = (idx >> 3) & 31;
        int tap   = idx >> 8;           // 0..8
        int mt = slot >> 2, fi = slot & 3;
        int co  = mt * 16 + (lane2 >> 2) + (fi & 1) * 8;
        int ci0 = 2 * (lane2 & 3) + (fi >> 1) * 8;
        float v0 = wgp[co * 144 + ci0 * 9 + tap];
        float v1 = wgp[co * 144 + (ci0 + 1) * 9 + tap];
        uint32_t lg = (uint32_t)(tap * 1024 + lane2 * 32 + slot * 4);
        *(uint32_t*)(swf + xswz(lg)) = h2pack(v0, v1);
    }
    if (tid < 32) sbias[tid] = bias[g * 32 + tid];
    __syncthreads();

    // ---- main: warp = (row pair rp, 32-px block wq); two 16-px halves ----
    const int rp = wid >> 2;             // 0..3 : output rows 2rp, 2rp+1
    const int wq = wid & 3;              // 0..3 : px block base wq*32
    const int l4 = lane >> 2;            // B n-index (pixel) / D m-row
    const int t4 = lane & 3;             // B k-pair / D px-pair
    float* og = out + (size_t)(n * 512 + g * 32) * 16384
                    + (size_t)(h0 + 2 * rp) * 128;

    const float b00 = sbias[l4];
    const float b01 = sbias[l4 + 8];
    const float b10 = sbias[16 + l4];
    const float b11 = sbias[16 + l4 + 8];

    const uint32_t bswF = xswz((uint32_t)(lane * 32));
    // x addr = (2rp + q)*XROW + (pxb + nt*8 + dw + l4)*32 + t4*4
    const uint32_t xinv = (uint32_t)(2 * rp * XROW_STRIDE + l4 * XCOL_STRIDE + t4 * 4);

    #pragma unroll
    for (int half = 0; half < 2; ++half) {
        const int pxb = wq * 32 + half * 16;
        float acc[2][2][2][4];           // [row][nt][mt][4]
        #pragma unroll
        for (int r = 0; r < 2; ++r)
            #pragma unroll
            for (int i = 0; i < 2; ++i)
                #pragma unroll
                for (int m = 0; m < 2; ++m)
                    #pragma unroll
                    for (int k = 0; k < 4; ++k) acc[r][i][m][k] = 0.0f;

        #pragma unroll
        for (int dw = 0; dw < 3; ++dw) {
            const uint32_t cb = xinv + (uint32_t)((pxb + dw) * XCOL_STRIDE);
            uint32_t Bc[2][2][2];        // [slot][nt][kpair]
            // preload q=0 -> slot0, q=1 -> slot1
            #pragma unroll
            for (int q = 0; q < 2; ++q) {
                #pragma unroll
                for (int nt = 0; nt < 2; ++nt) {
                    uint32_t ph = xswz(cb + (uint32_t)(q * XROW_STRIDE + nt * 8 * XCOL_STRIDE));
                    Bc[q][nt][0] = *(const uint32_t*)(sx + ph);
                    Bc[q][nt][1] = *(const uint32_t*)(sx + (ph ^ 16));
                }
            }
            #pragma unroll
            for (int dh = 0; dh < 3; ++dh) {
                // A fragments for tap (dh, dw)
                const uint32_t bo = (uint32_t)((dh * 3 + dw) * 1024) + bswF;
                uint4 awA = *(const uint4*)(swf + bo);          // mt0
                uint4 awB = *(const uint4*)(swf + (bo ^ 16));   // mt1

                const int s0 = dh & 1;          // slot holding q = dh
                const int s1 = (dh + 1) & 1;    // slot holding q = dh+1

                #pragma unroll
                for (int nt = 0; nt < 2; ++nt) {
                    mma16816(acc[0][nt][0][0], acc[0][nt][0][1], acc[0][nt][0][2], acc[0][nt][0][3],
                             awA.x, awA.y, awA.z, awA.w, Bc[s0][nt][0], Bc[s0][nt][1]);
                    mma16816(acc[0][nt][1][0], acc[0][nt][1][1], acc[0][nt][1][2], acc[0][nt][1][3],
                             awB.x, awB.y, awB.z, awB.w, Bc[s0][nt][0], Bc[s0][nt][1]);
                    mma16816(acc[1][nt][0][0], acc[1][nt][0][1], acc[1][nt][0][2], acc[1][nt][0][3],
                             awA.x, awA.y, awA.z, awA.w, Bc[s1][nt][0], Bc[s1][nt][1]);
                    mma16816(acc[1][nt][1][0], acc[1][nt][1][1], acc[1][nt][1][2], acc[1][nt][1][3],
                             awB.x, awB.y, awB.z, awB.w, Bc[s1][nt][0], Bc[s1][nt][1]);
                }

                // roll cache: load q = dh+2 into the slot that held q = dh
                if (dh < 2) {
                    #pragma unroll
                    for (int nt = 0; nt < 2; ++nt) {
                        uint32_t ph = xswz(cb + (uint32_t)((dh + 2) * XROW_STRIDE
                                                         + nt * 8 * XCOL_STRIDE));
                        Bc[s0][nt][0] = *(const uint32_t*)(sx + ph);
                        Bc[s0][nt][1] = *(const uint32_t*)(sx + (ph ^ 16));
                    }
                }
            }
        }

        // ---- epilogue: 2 rows, adjacent-px float2 stores ----
        #pragma unroll
        for (int r = 0; r < 2; ++r) {
            float* ogr = og + r * 128;
            #pragma unroll
            for (int nt = 0; nt < 2; ++nt) {
                const int px = pxb + nt * 8 + 2 * t4;
                #pragma unroll
                for (int mt = 0; mt < 2; ++mt) {
                    const float blo = mt ? b10 : b00;
                    const float bhi = mt ? b11 : b01;
                    float2 v01, v23;
                    v01.x = acc[r][nt][mt][0] + blo;
                    v01.y = acc[r][nt][mt][1] + blo;
                    v23.x = acc[r][nt][mt][2] + bhi;
                    v23.y = acc[r][nt][mt][3] + bhi;
                    *(float2*)(ogr + (size_t)(mt * 16 + l4) * 16384 + px)     = v01;
                    *(float2*)(ogr + (size_t)(mt * 16 + l4 + 8) * 16384 + px) = v23;
                }
            }
        }
    }
}

extern "C" void kernel_launch(void* const* d_in, const int* in_sizes, int n_in,
                              void* d_out, int out_size)
{
    const float* x = (const float*)d_in[0];
    const float* w = (const float*)d_in[1];
    const float* b = (const float*)d_in[2];
    float* out = (float*)d_out;

    cudaFuncSetAttribute(grouped_conv_hmma,
                         cudaFuncAttributeMaxDynamicSharedMemorySize, SMEM_TOTAL);

    dim3 grid(128 / ROWS, 256);   // 8-row h blocks, n*16+g
    grouped_conv_hmma<<<grid, THREADS, SMEM_TOTAL>>>(x, w, b, out);
}

// round 14
// speedup vs baseline: 2.0151x; 2.0151x over previous
#include <cuda_runtime.h>
#include <cuda_fp16.h>
#include <cstdint>

// Grouped conv2d via implicit GEMM on mma.sync (HMMA), single-pass fp16.
// x[16,256,128,128] * W[512,16,3,3] (groups=16) + b -> out[16,512,128,128]
// R14: R12 + row-pair B reuse, register-safe:
//   - LDS.64 x B-frags (phys slot order 2t4 / 2t4+1 -> one uint2 per nt)
//   - rolling 2-slot B cache shared by 2 output rows (B loads 6 -> 4 per dw)
//   - biases/og materialized in epilogue only; half loop not unrolled.

#define THREADS 512
#define ROWS 8

// ---- smem layout (bytes) ----
#define SWF_OFF   0
#define SWF_BYTES (9 * 1024)                // W frags: 9 taps x 32 lanes x 32B
#define XCOL_STRIDE 32
#define XROW_STRIDE (130 * XCOL_STRIDE)     // 4160
#define SX_OFF    SWF_BYTES                 // 9216
#define SX_BYTES  (10 * XROW_STRIDE)        // 41600 (ROWS+2 halo rows)
#define SBIAS_OFF (SX_OFF + SX_BYTES)       // 50816
#define SMEM_TOTAL (SBIAS_OFF + 128)        // 50944  (x2 CTA = 102KB <= 228KB)

__device__ __forceinline__ void mma16816(float& c0, float& c1, float& c2, float& c3,
                                         uint32_t a0, uint32_t a1, uint32_t a2, uint32_t a3,
                                         uint32_t b0, uint32_t b1) {
    asm volatile("mma.sync.aligned.m16n8k16.row.col.f32.f16.f16.f32 "
                 "{%0,%1,%2,%3}, {%4,%5,%6,%7}, {%8,%9}, {%0,%1,%2,%3};"
                 : "+f"(c0), "+f"(c1), "+f"(c2), "+f"(c3)
                 : "r"(a0), "r"(a1), "r"(a2), "r"(a3), "r"(b0), "r"(b1));
}

__device__ __forceinline__ uint32_t h2pack(float v0, float v1) {
    __half2 h = __floats2half2_rn(v0, v1);
    return *(uint32_t*)&h;
}

// fold addr bit7 into bit4 (16B-block xor; preserves 8B/16B alignment)
__device__ __forceinline__ uint32_t xswz(uint32_t a) {
    return a ^ (((a >> 7) & 1u) << 4);
}

__global__ __launch_bounds__(THREADS, 2)
void grouped_conv_hmma(const float* __restrict__ x,
                       const float* __restrict__ w,
                       const float* __restrict__ bias,
                       float* __restrict__ out)
{
    extern __shared__ char smem[];
    char* swf = smem + SWF_OFF;
    char* sx  = smem + SX_OFF;
    float* sbias = (float*)(smem + SBIAS_OFF);

    const int tid = threadIdx.x;
    const int wid = tid >> 5;
    const int lane = tid & 31;

    const int hb = blockIdx.x;          // 0..15  (8-row blocks)
    const int ng = blockIdx.y;          // 0..255
    const int n  = ng >> 4;
    const int g  = ng & 15;
    const int h0 = hb * ROWS;

    // ---- stage x: rows h0-1..h0+8 (r 0..9), cols c 0..129 (gw = c-1) ----
    // phys slot p: even p=2m -> ci pair m (ci 2m,2m+1); odd p=2m+1 -> pair m+4.
    // thread hf covers phys 4hf..4hf+3 = pairs {2hf, 2hf+4, 2hf+1, 2hf+5}.
    const float* xg = x + (size_t)(n * 256 + g * 16) * 16384;
    for (int idx = tid; idx < 10 * 2 * 130; idx += THREADS) {
        int c  = idx % 130;
        int t  = idx / 130;
        int hf = t & 1;
        int r  = t >> 1;                // 0..9
        int gh = h0 - 1 + r;
        int gw = c - 1;
        uint4 u = make_uint4(0u, 0u, 0u, 0u);
        if ((unsigned)gh < 128u && (unsigned)gw < 128u) {
            const float* p = xg + gh * 128 + gw;
            const int pr0 = 2 * hf;       // pairs: pr0, pr0+4, pr0+1, pr0+5
            u.x = h2pack(p[(size_t)(2 * pr0)     * 16384], p[(size_t)(2 * pr0 + 1)  * 16384]);
            u.y = h2pack(p[(size_t)(2 * pr0 + 8) * 16384], p[(size_t)(2 * pr0 + 9)  * 16384]);
            u.z = h2pack(p[(size_t)(2 * pr0 + 2) * 16384], p[(size_t)(2 * pr0 + 3)  * 16384]);
            u.w = h2pack(p[(size_t)(2 * pr0 + 10) * 16384], p[(size_t)(2 * pr0 + 11) * 16384]);
        }
        uint32_t lg = (uint32_t)(r * XROW_STRIDE + c * XCOL_STRIDE + hf * 16);
        *(uint4*)(sx + xswz(lg)) = u;
    }

    // ---- stage W as A fragments (m16k16), unchanged from R12 ----
    const float* wgp = w + (size_t)(g * 32) * 144;
    for (int idx = tid; idx < 9 * 32 * 8; idx += THREADS) {
        int slot  = idx & 7;
        int lane2 = (idx >> 3) & 31;
        int tap   = idx >> 8;           // 0..8
        int mt = slot >> 2, fi = slot & 3;
        int co  = mt * 16 + (lane2 >> 2) + (fi & 1) * 8;
        int ci0 = 2 * (lane2 & 3) + (fi >> 1) * 8;
        float v0 = wgp[co * 144 + ci0 * 9 + tap];
        float v1 = wgp[co * 144 + (ci0 + 1) * 9 + tap];
        uint32_t lg = (uint32_t)(tap * 1024 + lane2 * 32 + slot * 4);
        *(uint32_t*)(swf + xswz(lg)) = h2pack(v0, v1);
    }
    if (tid < 32) sbias[tid] = bias[g * 32 + tid];
    __syncthreads();

    // ---- main: warp = (row pair rp, 32-px block wq); two 16-px halves ----
    const int rp = wid >> 2;             // 0..3 : output rows 2rp, 2rp+1
    const int wq = wid & 3;              // 0..3 : px base wq*32
    const int l4 = lane >> 2;
    const int t4 = lane & 3;

    const uint32_t bswF = xswz((uint32_t)(lane * 32));
    const uint32_t xinv = (uint32_t)(2 * rp * XROW_STRIDE + l4 * XCOL_STRIDE + t4 * 8);

    #pragma unroll 1
    for (int half = 0; half < 2; ++half) {
        const int pxb = wq * 32 + half * 16;
        float acc[2][2][2][4];           // [row][nt][mt][4]
        #pragma unroll
        for (int r = 0; r < 2; ++r)
            #pragma unroll
            for (int i = 0; i < 2; ++i)
                #pragma unroll
                for (int m = 0; m < 2; ++m)
                    #pragma unroll
                    for (int k = 0; k < 4; ++k) acc[r][i][m][k] = 0.0f;

        #pragma unroll
        for (int dw = 0; dw < 3; ++dw) {
            const uint32_t cb = xinv + (uint32_t)((pxb + dw) * XCOL_STRIDE);
            uint2 Bc[2][2];              // [slot][nt]
            #pragma unroll
            for (int q = 0; q < 2; ++q)
                #pragma unroll
                for (int nt = 0; nt < 2; ++nt)
                    Bc[q][nt] = *(const uint2*)(sx + xswz(cb + (uint32_t)(q * XROW_STRIDE + nt * 256)));

            #pragma unroll
            for (int dh = 0; dh < 3; ++dh) {
                const uint32_t bo = (uint32_t)((dh * 3 + dw) * 1024) + bswF;
                uint4 awA = *(const uint4*)(swf + bo);          // mt0
                uint4 awB = *(const uint4*)(swf + (bo ^ 16));   // mt1
                const int s0 = dh & 1;          // slot holding q = dh (row 0)
                const int s1 = (dh + 1) & 1;    // slot holding q = dh+1 (row 1)

                #pragma unroll
                for (int nt = 0; nt < 2; ++nt) {
                    mma16816(acc[0][nt][0][0], acc[0][nt][0][1], acc[0][nt][0][2], acc[0][nt][0][3],
                             awA.x, awA.y, awA.z, awA.w, Bc[s0][nt].x, Bc[s0][nt].y);
                    mma16816(acc[0][nt][1][0], acc[0][nt][1][1], acc[0][nt][1][2], acc[0][nt][1][3],
                             awB.x, awB.y, awB.z, awB.w, Bc[s0][nt].x, Bc[s0][nt].y);
                    mma16816(acc[1][nt][0][0], acc[1][nt][0][1], acc[1][nt][0][2], acc[1][nt][0][3],
                             awA.x, awA.y, awA.z, awA.w, Bc[s1][nt].x, Bc[s1][nt].y);
                    mma16816(acc[1][nt][1][0], acc[1][nt][1][1], acc[1][nt][1][2], acc[1][nt][1][3],
                             awB.x, awB.y, awB.z, awB.w, Bc[s1][nt].x, Bc[s1][nt].y);
                }
                if (dh < 2) {
                    #pragma unroll
                    for (int nt = 0; nt < 2; ++nt)
                        Bc[s0][nt] = *(const uint2*)(sx + xswz(cb + (uint32_t)((dh + 2) * XROW_STRIDE + nt * 256)));
                }
            }
        }

        // ---- epilogue: biases + output pointer materialized here ----
        float* og = out + (size_t)(n * 512 + g * 32) * 16384
                        + (size_t)(h0 + 2 * rp) * 128;
        #pragma unroll
        for (int r = 0; r < 2; ++r) {
            float* ogr = og + r * 128;
            #pragma unroll
            for (int nt = 0; nt < 2; ++nt) {
                const int px = pxb + nt * 8 + 2 * t4;
                #pragma unroll
                for (int mt = 0; mt < 2; ++mt) {
                    const float blo = sbias[mt * 16 + l4];
                    const float bhi = sbias[mt * 16 + l4 + 8];
                    float2 v01, v23;
                    v01.x = acc[r][nt][mt][0] + blo;
                    v01.y = acc[r][nt][mt][1] + blo;
                    v23.x = acc[r][nt][mt][2] + bhi;
                    v23.y = acc[r][nt][mt][3] + bhi;
                    *(float2*)(ogr + (size_t)(mt * 16 + l4) * 16384 + px)     = v01;
                    *(float2*)(ogr + (size_t)(mt * 16 + l4 + 8) * 16384 + px) = v23;
                }
            }
        }
    }
}

extern "C" void kernel_launch(void* const* d_in, const int* in_sizes, int n_in,
                              void* d_out, int out_size)
{
    const float* x = (const float*)d_in[0];
    const float* w = (const float*)d_in[1];
    const float* b = (const float*)d_in[2];
    float* out = (float*)d_out;

    cudaFuncSetAttribute(grouped_conv_hmma,
                         cudaFuncAttributeMaxDynamicSharedMemorySize, SMEM_TOTAL);

    dim3 grid(128 / ROWS, 256);   // 8-row h blocks, n*16+g
    grouped_conv_hmma<<<grid, THREADS, SMEM_TOTAL>>>(x, w, b, out);
}

// round 15
// speedup vs baseline: 2.2320x; 1.1076x over previous
#include <cuda_runtime.h>
#include <cuda_fp16.h>
#include <cstdint>

// Grouped conv2d via implicit GEMM on mma.sync (HMMA), single-pass fp16.
// x[16,256,128,128] * W[512,16,3,3] (groups=16) + b -> out[16,512,128,128]
// R15: memory-instruction diet (L1 pipe ~4cyc/instr regardless of width):
//   - x smem as row-pair cells: 1 LDS.128 = B frags for 2 input rows
//     (B loads 48 LDS.64 -> 24 LDS.128 per warp)
//   - staging: 8 LDG.128 + 4 STS.128 per thread-unit (vectorized)
//   - slot-rotation swizzle keeps mainloop conflict-free.

#define THREADS 512
#define ROWS 8

// ---- smem layout (bytes) ----
#define SWF_OFF   0
#define SWF_BYTES (9 * 1024)                // W frags: 9 taps x 32 lanes x 32B
// x: [row-pair p 0..4][c 0..129][slot 0..3] 16B cells {row-even 8B, row-odd 8B}
#define PSTRIDE   (130 * 64)                // 8320
#define SX_OFF    SWF_BYTES                 // 9216
#define SX_BYTES  (5 * PSTRIDE)             // 41600
#define SBIAS_OFF (SX_OFF + SX_BYTES)       // 50816
#define SMEM_TOTAL (SBIAS_OFF + 128)        // 50944  (x2 CTA = 102KB)

__device__ __forceinline__ void mma16816(float& c0, float& c1, float& c2, float& c3,
                                         uint32_t a0, uint32_t a1, uint32_t a2, uint32_t a3,
                                         uint32_t b0, uint32_t b1) {
    asm volatile("mma.sync.aligned.m16n8k16.row.col.f32.f16.f16.f32 "
                 "{%0,%1,%2,%3}, {%4,%5,%6,%7}, {%8,%9}, {%0,%1,%2,%3};"
                 : "+f"(c0), "+f"(c1), "+f"(c2), "+f"(c3)
                 : "r"(a0), "r"(a1), "r"(a2), "r"(a3), "r"(b0), "r"(b1));
}

__device__ __forceinline__ uint32_t h2pack(float v0, float v1) {
    __half2 h = __floats2half2_rn(v0, v1);
    return *(uint32_t*)&h;
}

// W-frag swizzle (unchanged, bit7->bit4)
__device__ __forceinline__ uint32_t wswz(uint32_t a) {
    return a ^ (((a >> 7) & 1u) << 4);
}
// x cell address: slot rotated by c-quad (conflict-free mainloop LDS.128)
__device__ __forceinline__ uint32_t xaddr(int p, int c, int slot) {
    return (uint32_t)(p * PSTRIDE + c * 64 + ((slot ^ ((c >> 2) & 3)) << 4));
}

__global__ __launch_bounds__(THREADS, 2)
void grouped_conv_hmma(const float* __restrict__ x,
                       const float* __restrict__ w,
                       const float* __restrict__ bias,
                       float* __restrict__ out)
{
    extern __shared__ char smem[];
    char* swf = smem + SWF_OFF;
    char* sx  = smem + SX_OFF;
    float* sbias = (float*)(smem + SBIAS_OFF);

    const int tid = threadIdx.x;
    const int wid = tid >> 5;
    const int lane = tid & 31;

    const int hb = blockIdx.x;          // 0..15  (8-row blocks)
    const int ng = blockIdx.y;          // 0..255
    const int n  = ng >> 4;
    const int g  = ng & 15;
    const int h0 = hb * ROWS;

    // ---- stage x: 640 units = (p 0..4, slot 0..3, gw-quad 0..31) ----
    // cell (p,c,slot) = 16B: {row 2p: half2(ci 2s,2s+1), half2(ci 2s+8,2s+9),
    //                          row 2p+1: same}
    const float* xg = x + (size_t)(n * 256 + g * 16) * 16384;
    #pragma unroll
    for (int it = 0; it < 2; ++it) {
        int su = tid + it * THREADS;
        if (su < 640) {
            int qd   = su & 31;
            int slot = (su >> 5) & 3;
            int p    = su >> 7;          // 0..4
            int gw0  = qd * 4;
            float v[2][4][4];            // [row][plane e][k]
            #pragma unroll
            for (int rr = 0; rr < 2; ++rr) {
                int gh = h0 - 1 + 2 * p + rr;
                if ((unsigned)gh < 128u) {
                    const float* base = xg + gh * 128 + gw0;
                    *(float4*)v[rr][0] = *(const float4*)(base + (size_t)(2 * slot)     * 16384);
                    *(float4*)v[rr][1] = *(const float4*)(base + (size_t)(2 * slot + 1) * 16384);
                    *(float4*)v[rr][2] = *(const float4*)(base + (size_t)(2 * slot + 8) * 16384);
                    *(float4*)v[rr][3] = *(const float4*)(base + (size_t)(2 * slot + 9) * 16384);
                } else {
                    #pragma unroll
                    for (int e = 0; e < 4; ++e)
                        #pragma unroll
                        for (int k = 0; k < 4; ++k) v[rr][e][k] = 0.0f;
                }
            }
            #pragma unroll
            for (int k = 0; k < 4; ++k) {
                int c = gw0 + 1 + k;
                uint4 cell;
                cell.x = h2pack(v[0][0][k], v[0][1][k]);
                cell.y = h2pack(v[0][2][k], v[0][3][k]);
                cell.z = h2pack(v[1][0][k], v[1][1][k]);
                cell.w = h2pack(v[1][2][k], v[1][3][k]);
                *(uint4*)(sx + xaddr(p, c, slot)) = cell;
            }
        }
    }
    // zero edge cells c=0, c=129
    if (tid < 40) {
        int slot = tid & 3;
        int c    = ((tid >> 2) & 1) ? 129 : 0;
        int p    = tid >> 3;            // 0..4
        uint4 z = make_uint4(0u, 0u, 0u, 0u);
        *(uint4*)(sx + xaddr(p, c, slot)) = z;
    }

    // ---- stage W as A fragments (m16k16), unchanged ----
    const float* wgp = w + (size_t)(g * 32) * 144;
    for (int idx = tid; idx < 9 * 32 * 8; idx += THREADS) {
        int slot  = idx & 7;
        int lane2 = (idx >> 3) & 31;
        int tap   = idx >> 8;           // 0..8
        int mt = slot >> 2, fi = slot & 3;
        int co  = mt * 16 + (lane2 >> 2) + (fi & 1) * 8;
        int ci0 = 2 * (lane2 & 3) + (fi >> 1) * 8;
        float v0 = wgp[co * 144 + ci0 * 9 + tap];
        float v1 = wgp[co * 144 + (ci0 + 1) * 9 + tap];
        uint32_t lg = (uint32_t)(tap * 1024 + lane2 * 32 + slot * 4);
        *(uint32_t*)(swf + wswz(lg)) = h2pack(v0, v1);
    }
    if (tid < 32) sbias[tid] = bias[g * 32 + tid];
    __syncthreads();

    // ---- main: warp = (row pair rp, 32-px block wq); two 16-px halves ----
    // output rows 2rp, 2rp+1 need staged rows 2rp..2rp+3 = cells p=rp, rp+1.
    const int rp = wid >> 2;             // 0..3
    const int wq = wid & 3;              // px base wq*32
    const int l4 = lane >> 2;
    const int t4 = lane & 3;

    const uint32_t bswF = wswz((uint32_t)(lane * 32));

    #pragma unroll 1
    for (int half = 0; half < 2; ++half) {
        const int pxb = wq * 32 + half * 16;
        float acc[2][2][2][4];           // [row][nt][mt][4]
        #pragma unroll
        for (int r = 0; r < 2; ++r)
            #pragma unroll
            for (int i = 0; i < 2; ++i)
                #pragma unroll
                for (int m = 0; m < 2; ++m)
                    #pragma unroll
                    for (int k = 0; k < 4; ++k) acc[r][i][m][k] = 0.0f;

        #pragma unroll
        for (int dw = 0; dw < 3; ++dw) {
            // V[nt][j]: j=0 -> rows 2rp,2rp+1 (q0,q1); j=1 -> rows 2rp+2,2rp+3 (q2,q3)
            uint4 V[2][2];
            #pragma unroll
            for (int nt = 0; nt < 2; ++nt) {
                const int c = pxb + dw + nt * 8 + l4;
                const uint32_t ad = xaddr(rp, c, t4);
                V[nt][0] = *(const uint4*)(sx + ad);
                V[nt][1] = *(const uint4*)(sx + ad + PSTRIDE);
            }
            #pragma unroll
            for (int dh = 0; dh < 3; ++dh) {
                const uint32_t bo = (uint32_t)((dh * 3 + dw) * 1024) + bswF;
                uint4 awA = *(const uint4*)(swf + bo);          // mt0
                uint4 awB = *(const uint4*)(swf + (bo ^ 16));   // mt1

                #pragma unroll
                for (int nt = 0; nt < 2; ++nt) {
                    // row0 uses q=dh, row1 uses q=dh+1
                    uint32_t b0r0 = (dh == 0) ? V[nt][0].x : (dh == 1) ? V[nt][0].z : V[nt][1].x;
                    uint32_t b1r0 = (dh == 0) ? V[nt][0].y : (dh == 1) ? V[nt][0].w : V[nt][1].y;
                    uint32_t b0r1 = (dh == 0) ? V[nt][0].z : (dh == 1) ? V[nt][1].x : V[nt][1].z;
                    uint32_t b1r1 = (dh == 0) ? V[nt][0].w : (dh == 1) ? V[nt][1].y : V[nt][1].w;

                    mma16816(acc[0][nt][0][0], acc[0][nt][0][1], acc[0][nt][0][2], acc[0][nt][0][3],
                             awA.x, awA.y, awA.z, awA.w, b0r0, b1r0);
                    mma16816(acc[0][nt][1][0], acc[0][nt][1][1], acc[0][nt][1][2], acc[0][nt][1][3],
                             awB.x, awB.y, awB.z, awB.w, b0r0, b1r0);
                    mma16816(acc[1][nt][0][0], acc[1][nt][0][1], acc[1][nt][0][2], acc[1][nt][0][3],
                             awA.x, awA.y, awA.z, awA.w, b0r1, b1r1);
                    mma16816(acc[1][nt][1][0], acc[1][nt][1][1], acc[1][nt][1][2], acc[1][nt][1][3],
                             awB.x, awB.y, awB.z, awB.w, b0r1, b1r1);
                }
            }
        }

        // ---- epilogue ----
        float* og = out + (size_t)(n * 512 + g * 32) * 16384
                        + (size_t)(h0 + 2 * rp) * 128;
        #pragma unroll
        for (int r = 0; r < 2; ++r) {
            float* ogr = og + r * 128;
            #pragma unroll
            for (int nt = 0; nt < 2; ++nt) {
                const int px = pxb + nt * 8 + 2 * t4;
                #pragma unroll
                for (int mt = 0; mt < 2; ++mt) {
                    const float blo = sbias[mt * 16 + l4];
                    const float bhi = sbias[mt * 16 + l4 + 8];
                    float2 v01, v23;
                    v01.x = acc[r][nt][mt][0] + blo;
                    v01.y = acc[r][nt][mt][1] + blo;
                    v23.x = acc[r][nt][mt][2] + bhi;
                    v23.y = acc[r][nt][mt][3] + bhi;
                    *(float2*)(ogr + (size_t)(mt * 16 + l4) * 16384 + px)     = v01;
                    *(float2*)(ogr + (size_t)(mt * 16 + l4 + 8) * 16384 + px) = v23;
                }
            }
        }
    }
}

extern "C" void kernel_launch(void* const* d_in, const int* in_sizes, int n_in,
                              void* d_out, int out_size)
{
    const float* x = (const float*)d_in[0];
    const float* w = (const float*)d_in[1];
    const float* b = (const float*)d_in[2];
    float* out = (float*)d_out;

    cudaFuncSetAttribute(grouped_conv_hmma,
                         cudaFuncAttributeMaxDynamicSharedMemorySize, SMEM_TOTAL);

    dim3 grid(128 / ROWS, 256);   // 8-row h blocks, n*16+g
    grouped_conv_hmma<<<grid, THREADS, SMEM_TOTAL>>>(x, w, b, out);
}

// round 16
// speedup vs baseline: 2.3929x; 1.0721x over previous
#include <cuda_runtime.h>
#include <cuda_fp16.h>
#include <cstdint>

// Grouped conv2d via implicit GEMM on mma.sync (HMMA), single-pass fp16.
// x[16,256,128,128] * W[512,16,3,3] (groups=16) + b -> out[16,512,128,128]
// R16 = R15 + weight pre-formatting kernel:
//   pre-kernel writes fragment-layout swizzled fp16 weights per group to a
//   __device__ scratch; main kernel stages W with a coalesced 9KB copy
//   (144 wf vs ~4500 wf of scattered scalar LDG per CTA).

#define THREADS 512
#define ROWS 8

// ---- smem layout (bytes) ----
#define SWF_OFF   0
#define SWF_BYTES (9 * 1024)                // W frags: 9 taps x 32 lanes x 32B
// x: [row-pair p 0..4][c 0..129][slot 0..3] 16B cells {row-even 8B, row-odd 8B}
#define PSTRIDE   (130 * 64)                // 8320
#define SX_OFF    SWF_BYTES                 // 9216
#define SX_BYTES  (5 * PSTRIDE)             // 41600
#define SBIAS_OFF (SX_OFF + SX_BYTES)       // 50816
#define SMEM_TOTAL (SBIAS_OFF + 128)        // 50944  (x2 CTA = 102KB)

// fragment-formatted weights for all 16 groups (filled by prep_weights)
__device__ uint32_t g_wfrag[16 * 2304];

__device__ __forceinline__ void mma16816(float& c0, float& c1, float& c2, float& c3,
                                         uint32_t a0, uint32_t a1, uint32_t a2, uint32_t a3,
                                         uint32_t b0, uint32_t b1) {
    asm volatile("mma.sync.aligned.m16n8k16.row.col.f32.f16.f16.f32 "
                 "{%0,%1,%2,%3}, {%4,%5,%6,%7}, {%8,%9}, {%0,%1,%2,%3};"
                 : "+f"(c0), "+f"(c1), "+f"(c2), "+f"(c3)
                 : "r"(a0), "r"(a1), "r"(a2), "r"(a3), "r"(b0), "r"(b1));
}

__device__ __forceinline__ uint32_t h2pack(float v0, float v1) {
    __half2 h = __floats2half2_rn(v0, v1);
    return *(uint32_t*)&h;
}

// W-frag swizzle (bit7->bit4, 16B blocks)
__device__ __forceinline__ uint32_t wswz(uint32_t a) {
    return a ^ (((a >> 7) & 1u) << 4);
}
// x cell address: slot rotated by c-quad (conflict-free mainloop LDS.128)
__device__ __forceinline__ uint32_t xaddr(int p, int c, int slot) {
    return (uint32_t)(p * PSTRIDE + c * 64 + ((slot ^ ((c >> 2) & 3)) << 4));
}

// ---- pre-kernel: scatter-gather weights ONCE into fragment layout ----
__global__ void prep_weights(const float* __restrict__ w) {
    const int g = blockIdx.x;
    const float* wgp = w + (size_t)(g * 32) * 144;
    for (int idx = threadIdx.x; idx < 2304; idx += 256) {
        int slot  = idx & 7;
        int lane2 = (idx >> 3) & 31;
        int tap   = idx >> 8;           // 0..8
        int mt = slot >> 2, fi = slot & 3;
        int co  = mt * 16 + (lane2 >> 2) + (fi & 1) * 8;
        int ci0 = 2 * (lane2 & 3) + (fi >> 1) * 8;
        float v0 = wgp[co * 144 + ci0 * 9 + tap];
        float v1 = wgp[co * 144 + (ci0 + 1) * 9 + tap];
        uint32_t lg = (uint32_t)(tap * 1024 + lane2 * 32 + slot * 4);
        g_wfrag[g * 2304 + (wswz(lg) >> 2)] = h2pack(v0, v1);
    }
}

__global__ __launch_bounds__(THREADS, 2)
void grouped_conv_hmma(const float* __restrict__ x,
                       const float* __restrict__ w,
                       const float* __restrict__ bias,
                       float* __restrict__ out)
{
    extern __shared__ char smem[];
    char* swf = smem + SWF_OFF;
    char* sx  = smem + SX_OFF;
    float* sbias = (float*)(smem + SBIAS_OFF);

    const int tid = threadIdx.x;
    const int wid = tid >> 5;
    const int lane = tid & 31;

    const int hb = blockIdx.x;          // 0..15  (8-row blocks)
    const int ng = blockIdx.y;          // 0..255
    const int n  = ng >> 4;
    const int g  = ng & 15;
    const int h0 = hb * ROWS;

    // ---- stage x: 640 units = (p 0..4, slot 0..3, gw-quad 0..31) ----
    const float* xg = x + (size_t)(n * 256 + g * 16) * 16384;
    #pragma unroll
    for (int it = 0; it < 2; ++it) {
        int su = tid + it * THREADS;
        if (su < 640) {
            int qd   = su & 31;
            int slot = (su >> 5) & 3;
            int p    = su >> 7;          // 0..4
            int gw0  = qd * 4;
            float v[2][4][4];            // [row][plane e][k]
            #pragma unroll
            for (int rr = 0; rr < 2; ++rr) {
                int gh = h0 - 1 + 2 * p + rr;
                if ((unsigned)gh < 128u) {
                    const float* base = xg + gh * 128 + gw0;
                    *(float4*)v[rr][0] = *(const float4*)(base + (size_t)(2 * slot)     * 16384);
                    *(float4*)v[rr][1] = *(const float4*)(base + (size_t)(2 * slot + 1) * 16384);
                    *(float4*)v[rr][2] = *(const float4*)(base + (size_t)(2 * slot + 8) * 16384);
                    *(float4*)v[rr][3] = *(const float4*)(base + (size_t)(2 * slot + 9) * 16384);
                } else {
                    #pragma unroll
                    for (int e = 0; e < 4; ++e)
                        #pragma unroll
                        for (int k = 0; k < 4; ++k) v[rr][e][k] = 0.0f;
                }
            }
            #pragma unroll
            for (int k = 0; k < 4; ++k) {
                int c = gw0 + 1 + k;
                uint4 cell;
                cell.x = h2pack(v[0][0][k], v[0][1][k]);
                cell.y = h2pack(v[0][2][k], v[0][3][k]);
                cell.z = h2pack(v[1][0][k], v[1][1][k]);
                cell.w = h2pack(v[1][2][k], v[1][3][k]);
                *(uint4*)(sx + xaddr(p, c, slot)) = cell;
            }
        }
    }
    // zero edge cells c=0, c=129
    if (tid < 40) {
        int slot = tid & 3;
        int c    = ((tid >> 2) & 1) ? 129 : 0;
        int p    = tid >> 3;            // 0..4
        uint4 z = make_uint4(0u, 0u, 0u, 0u);
        *(uint4*)(sx + xaddr(p, c, slot)) = z;
    }

    // ---- stage W: coalesced copy of pre-formatted fragments ----
    {
        const uint4* src = (const uint4*)(g_wfrag + g * 2304);
        uint4* dst = (uint4*)swf;
        for (int i = tid; i < 576; i += THREADS) dst[i] = src[i];
    }
    if (tid < 32) sbias[tid] = bias[g * 32 + tid];
    __syncthreads();

    // ---- main: warp = (row pair rp, 32-px block wq); two 16-px halves ----
    const int rp = wid >> 2;             // 0..3
    const int wq = wid & 3;              // px base wq*32
    const int l4 = lane >> 2;
    const int t4 = lane & 3;

    const uint32_t bswF = wswz((uint32_t)(lane * 32));

    #pragma unroll 1
    for (int half = 0; half < 2; ++half) {
        const int pxb = wq * 32 + half * 16;
        float acc[2][2][2][4];           // [row][nt][mt][4]
        #pragma unroll
        for (int r = 0; r < 2; ++r)
            #pragma unroll
            for (int i = 0; i < 2; ++i)
                #pragma unroll
                for (int m = 0; m < 2; ++m)
                    #pragma unroll
                    for (int k = 0; k < 4; ++k) acc[r][i][m][k] = 0.0f;

        #pragma unroll
        for (int dw = 0; dw < 3; ++dw) {
            // V[nt][j]: j=0 -> rows 2rp,2rp+1; j=1 -> rows 2rp+2,2rp+3
            uint4 V[2][2];
            #pragma unroll
            for (int nt = 0; nt < 2; ++nt) {
                const int c = pxb + dw + nt * 8 + l4;
                const uint32_t ad = xaddr(rp, c, t4);
                V[nt][0] = *(const uint4*)(sx + ad);
                V[nt][1] = *(const uint4*)(sx + ad + PSTRIDE);
            }
            #pragma unroll
            for (int dh = 0; dh < 3; ++dh) {
                const uint32_t bo = (uint32_t)((dh * 3 + dw) * 1024) + bswF;
                uint4 awA = *(const uint4*)(swf + bo);          // mt0
                uint4 awB = *(const uint4*)(swf + (bo ^ 16));   // mt1

                #pragma unroll
                for (int nt = 0; nt < 2; ++nt) {
                    uint32_t b0r0 = (dh == 0) ? V[nt][0].x : (dh == 1) ? V[nt][0].z : V[nt][1].x;
                    uint32_t b1r0 = (dh == 0) ? V[nt][0].y : (dh == 1) ? V[nt][0].w : V[nt][1].y;
                    uint32_t b0r1 = (dh == 0) ? V[nt][0].z : (dh == 1) ? V[nt][1].x : V[nt][1].z;
                    uint32_t b1r1 = (dh == 0) ? V[nt][0].w : (dh == 1) ? V[nt][1].y : V[nt][1].w;

                    mma16816(acc[0][nt][0][0], acc[0][nt][0][1], acc[0][nt][0][2], acc[0][nt][0][3],
                             awA.x, awA.y, awA.z, awA.w, b0r0, b1r0);
                    mma16816(acc[0][nt][1][0], acc[0][nt][1][1], acc[0][nt][1][2], acc[0][nt][1][3],
                             awB.x, awB.y, awB.z, awB.w, b0r0, b1r0);
                    mma16816(acc[1][nt][0][0], acc[1][nt][0][1], acc[1][nt][0][2], acc[1][nt][0][3],
                             awA.x, awA.y, awA.z, awA.w, b0r1, b1r1);
                    mma16816(acc[1][nt][1][0], acc[1][nt][1][1], acc[1][nt][1][2], acc[1][nt][1][3],
                             awB.x, awB.y, awB.z, awB.w, b0r1, b1r1);
                }
            }
        }

        // ---- epilogue ----
        float* og = out + (size_t)(n * 512 + g * 32) * 16384
                        + (size_t)(h0 + 2 * rp) * 128;
        #pragma unroll
        for (int r = 0; r < 2; ++r) {
            float* ogr = og + r * 128;
            #pragma unroll
            for (int nt = 0; nt < 2; ++nt) {
                const int px = pxb + nt * 8 + 2 * t4;
                #pragma unroll
                for (int mt = 0; mt < 2; ++mt) {
                    const float blo = sbias[mt * 16 + l4];
                    const float bhi = sbias[mt * 16 + l4 + 8];
                    float2 v01, v23;
                    v01.x = acc[r][nt][mt][0] + blo;
                    v01.y = acc[r][nt][mt][1] + blo;
                    v23.x = acc[r][nt][mt][2] + bhi;
                    v23.y = acc[r][nt][mt][3] + bhi;
                    *(float2*)(ogr + (size_t)(mt * 16 + l4) * 16384 + px)     = v01;
                    *(float2*)(ogr + (size_t)(mt * 16 + l4 + 8) * 16384 + px) = v23;
                }
            }
        }
    }
}

extern "C" void kernel_launch(void* const* d_in, const int* in_sizes, int n_in,
                              void* d_out, int out_size)
{
    const float* x = (const float*)d_in[0];
    const float* w = (const float*)d_in[1];
    const float* b = (const float*)d_in[2];
    float* out = (float*)d_out;

    cudaFuncSetAttribute(grouped_conv_hmma,
                         cudaFuncAttributeMaxDynamicSharedMemorySize, SMEM_TOTAL);

    prep_weights<<<16, 256>>>(w);

    dim3 grid(128 / ROWS, 256);   // 8-row h blocks, n*16+g
    grouped_conv_hmma<<<grid, THREADS, SMEM_TOTAL>>>(x, w, b, out);
}